// round 1
// baseline (speedup 1.0000x reference)
#include <cuda_runtime.h>
#include <math.h>

// ---------------------------------------------------------------------------
// Butterfly module: gather rows -> 4 rotation layers -> bias+smooth-relu on
// first 8 rows of each 16-block -> 4 rotation layers -> scatter rows.
// One thread owns a 16-row x 4-col (float4) slice; all 8 layers in registers.
// ---------------------------------------------------------------------------

#define CURV2 0.01f   // CURVATURE^2 = 0.1^2

__device__ __forceinline__ float smooth_relu(float xa) {
    return 0.5f * (xa + sqrtf(fmaf(xa, xa, CURV2)));
}

__device__ __forceinline__ void rot4(float4& a, float4& b, float c, float s) {
    float4 na, nb;
    na.x = fmaf(c, a.x, s * b.x);  nb.x = fmaf(c, b.x, -s * a.x);
    na.y = fmaf(c, a.y, s * b.y);  nb.y = fmaf(c, b.y, -s * a.y);
    na.z = fmaf(c, a.z, s * b.z);  nb.z = fmaf(c, b.z, -s * a.z);
    na.w = fmaf(c, a.w, s * b.w);  nb.w = fmaf(c, b.w, -s * a.w);
    a = na; b = nb;
}

// One butterfly layer with compile-time stride S. cs points at the 8
// (cos,sin) pairs for this layer, ordered by ascending low-row offset
// (matching the reference's ascending `low` enumeration).
template <int S>
__device__ __forceinline__ void blayer(float4 v[16], const float2* cs) {
    int p = 0;
#pragma unroll
    for (int o = 0; o < 16; ++o) {
        if ((o & S) == 0) {
            float2 a = cs[p];
            rot4(v[o], v[o + S], a.x, a.y);
            ++p;
        }
    }
}

__global__ __launch_bounds__(256)
void butterfly_kernel(const float* __restrict__ data,
                      const float* __restrict__ angles,
                      const float* __restrict__ biases,
                      const int*   __restrict__ idx_in,
                      const int*   __restrict__ idx_out,
                      float*       __restrict__ out,
                      int N, int B)
{
    __shared__ float2 cs[64];    // [layer 0..7][pair 0..7] -> (cos, sin)
    __shared__ float  sb[8];     // biases for this 16-block
    __shared__ int    rin[16], rout[16];

    const int tid = threadIdx.x;
    const int blk = blockIdx.y;          // 16-row block index

    if (tid < 64) {
        int l = tid >> 3, p = tid & 7;
        float a = angles[(size_t)l * (N >> 1) + blk * 8 + p];
        float s, c;
        sincosf(a, &s, &c);
        cs[tid] = make_float2(c, s);
    }
    if (tid < 8)  sb[tid] = biases[blk * 8 + tid];
    if (tid < 16) {
        rin[tid]  = idx_in[blk * 16 + tid];
        rout[tid] = idx_out[blk * 16 + tid];
    }
    __syncthreads();

    const int col = blockIdx.x * (blockDim.x * 4) + tid * 4;
    if (col >= B) return;

    float4 v[16];
#pragma unroll
    for (int o = 0; o < 16; ++o)
        v[o] = *reinterpret_cast<const float4*>(data + (size_t)rin[o] * B + col);

    // input layers: strides 1,2,4,8
    blayer<1>(v, cs + 0);
    blayer<2>(v, cs + 8);
    blayer<4>(v, cs + 16);
    blayer<8>(v, cs + 24);

    // fused bias + smooth relu on first 8 rows of the block
#pragma unroll
    for (int o = 0; o < 8; ++o) {
        float b = sb[o];
        v[o].x = smooth_relu(v[o].x + b);
        v[o].y = smooth_relu(v[o].y + b);
        v[o].z = smooth_relu(v[o].z + b);
        v[o].w = smooth_relu(v[o].w + b);
    }

    // output layers: strides 1,2,4,8
    blayer<1>(v, cs + 32);
    blayer<2>(v, cs + 40);
    blayer<4>(v, cs + 48);
    blayer<8>(v, cs + 56);

#pragma unroll
    for (int o = 0; o < 16; ++o)
        *reinterpret_cast<float4*>(out + (size_t)rout[o] * B + col) = v[o];
}

// ---------------------------------------------------------------------------
// Rows of `data` NOT targeted by idx_out must pass through unchanged
// (out = data.at[idx_out].set(x)). Mark covered rows, copy the rest.
// For the identity permutation these are near no-ops.
// ---------------------------------------------------------------------------

__device__ unsigned char g_covered[1 << 20];  // supports up to 1M rows

__global__ void zero_flags_kernel(int R) {
    int i = blockIdx.x * blockDim.x + threadIdx.x;
    if (i < R) g_covered[i] = 0;
}

__global__ void mark_flags_kernel(const int* __restrict__ idx_out, int N) {
    int i = blockIdx.x * blockDim.x + threadIdx.x;
    if (i < N) g_covered[idx_out[i]] = 1;
}

__global__ __launch_bounds__(256)
void copy_uncovered_kernel(const float* __restrict__ data,
                           float* __restrict__ out, int B) {
    int row = blockIdx.x;
    if (g_covered[row]) return;
    const float4* src = reinterpret_cast<const float4*>(data + (size_t)row * B);
    float4*       dst = reinterpret_cast<float4*>(out + (size_t)row * B);
    for (int i = threadIdx.x; i < (B >> 2); i += blockDim.x)
        dst[i] = src[i];
}

extern "C" void kernel_launch(void* const* d_in, const int* in_sizes, int n_in,
                              void* d_out, int out_size)
{
    const float* data    = (const float*)d_in[0];
    const float* angles  = (const float*)d_in[1];
    const float* biases  = (const float*)d_in[2];
    const int*   idx_in  = (const int*)d_in[3];
    const int*   idx_out = (const int*)d_in[4];
    float*       out     = (float*)d_out;

    const int N = in_sizes[3];            // number of gathered rows (4096)
    const int B = in_sizes[0] / N;        // row width (8192); data rows == N here
    const int R = out_size / B;           // rows in data/out

    // pass-through for rows not written by the scatter
    zero_flags_kernel<<<(R + 255) / 256, 256>>>(R);
    mark_flags_kernel<<<(N + 255) / 256, 256>>>(idx_out, N);
    copy_uncovered_kernel<<<R, 256>>>(data, out, B);

    // main fused butterfly
    dim3 grid((B + 1023) / 1024, N / 16);
    butterfly_kernel<<<grid, 256>>>(data, angles, biases, idx_in, idx_out,
                                    out, N, B);
}